// round 9
// baseline (speedup 1.0000x reference)
#include <cuda_runtime.h>
#include <cstdint>

// ---------------- problem constants ----------------
#define BATCH_N   1048576
#define IN_SZ     64
#define HID       16
#define KDIM      80          // IN_SZ + HID
#define NDIM      80          // 5 * HID
#define TILE_M    256         // 256 rows per CTA, warp owns 32 rows (2 m-tiles)
#define NTHREADS  256

// A smem: fragment-packed. Per 16-row tile: [kt=10][qr=8][phys qc=4][4 floats]
#define A_TILE_FLOATS 1280
#define N_TILES       (TILE_M / 16)            // 16
#define A_FLOATS      (N_TILES * A_TILE_FLOATS) // 20480
// B fragments in smem: [kt=10][np=5][lane=32][4] = 6400
#define BFRAG_FLOATS  6400
#define SMEM_FLOATS   (A_FLOATS + BFRAG_FLOATS + NDIM)
#define SMEM_BYTES    (SMEM_FLOATS * 4)        // 107840 (~105.3 KB) -> 2 CTAs/SM

__device__ uint32_t g_Bfrag[BFRAG_FLOATS];
__device__ float    g_bias[NDIM];

static __device__ __forceinline__ uint32_t f2tf32(float f) {
    uint32_t u;
    asm("cvt.rna.tf32.f32 %0, %1;" : "=r"(u) : "f"(f));
    return u;
}

static __device__ __forceinline__ void mma_tf32(float* c, const uint32_t* a,
                                                uint32_t b0, uint32_t b1) {
    asm volatile(
        "mma.sync.aligned.m16n8k8.row.col.f32.tf32.tf32.f32 "
        "{%0,%1,%2,%3}, {%4,%5,%6,%7}, {%8,%9}, {%0,%1,%2,%3};"
        : "+f"(c[0]), "+f"(c[1]), "+f"(c[2]), "+f"(c[3])
        : "r"(a[0]), "r"(a[1]), "r"(a[2]), "r"(a[3]), "r"(b0), "r"(b1));
}

static __device__ __forceinline__ float tanh_fast(float x) {
    float e = __expf(-2.0f * fabsf(x));
    float t = __fdividef(1.0f - e, 1.0f + e);
    return copysignf(t, x);
}
static __device__ __forceinline__ float softplus_fast(float x) {
    return fmaxf(x, 0.0f) + __logf(1.0f + __expf(-fabsf(x)));
}

// ---------------- prep: pack W into per-lane mma B-fragments + bias ----------------
// g_Bfrag index i = ((kt*5 + np)*32 + lane)*4 + slot
//   lane = qr*4 + qc ; nt = 2*np + (slot>>1) ; pos = slot&1
//   value = tf32( W[k = kt*8 + qc + 4*pos][n = nt*8 + qr] )
__global__ void prep_kernel(
    const float* __restrict__ W_i, const float* __restrict__ b_i,
    const float* __restrict__ W_f, const float* __restrict__ b_f,
    const float* __restrict__ W_o, const float* __restrict__ b_o,
    const float* __restrict__ W_c, const float* __restrict__ b_c,
    const float* __restrict__ W_d, const float* __restrict__ b_d)
{
    int i = blockIdx.x * blockDim.x + threadIdx.x;
    if (i < BFRAG_FLOATS) {
        int slot = i & 3;
        int lane = (i >> 2) & 31;
        int rest = i >> 7;            // 0..49
        int np = rest % 5;
        int kt = rest / 5;
        int qr = lane >> 2;
        int qc = lane & 3;
        int nt = 2 * np + (slot >> 1);
        int pos = slot & 1;
        int k = kt * 8 + qc + 4 * pos;
        int n = nt * 8 + qr;
        int g = n >> 4, c = n & 15;
        const float* W = (g == 0) ? W_i : (g == 1) ? W_f : (g == 2) ? W_o
                       : (g == 3) ? W_c : W_d;
        g_Bfrag[i] = f2tf32(W[k * HID + c]);
    } else if (i < BFRAG_FLOATS + NDIM) {
        int n = i - BFRAG_FLOATS;
        int g = n >> 4, c = n & 15;
        const float* B = (g == 0) ? b_i : (g == 1) ? b_f : (g == 2) ? b_o
                       : (g == 3) ? b_c : b_d;
        g_bias[n] = B[c];
    }
}

__global__ void __launch_bounds__(NTHREADS, 2) ctlstm_kernel(
    const float* __restrict__ x,
    const float* __restrict__ h_prev,
    const float* __restrict__ c_prev,
    const float* __restrict__ delta_t,
    float* __restrict__ out_h, float* __restrict__ out_c)
{
    extern __shared__ uint32_t smem[];
    uint32_t* As = smem;                                        // fragment-packed A
    uint32_t* Bs = smem + A_FLOATS;                             // fragment-packed B
    float*    bs = reinterpret_cast<float*>(smem + A_FLOATS + BFRAG_FLOATS); // bias

    const int tid  = threadIdx.x;
    const int warp = tid >> 5;
    const int lane = tid & 31;
    const int qr   = lane >> 2;   // 0..7
    const int qc   = lane & 3;    // 0..3
    const int row0 = blockIdx.x * TILE_M;

    // ---- B fragments + bias: coalesced copy from precomputed globals ----
    {
        const uint4* src = reinterpret_cast<const uint4*>(g_Bfrag);
        uint4* dst = reinterpret_cast<uint4*>(Bs);
        #pragma unroll
        for (int it = 0; it < (BFRAG_FLOATS / 4 + NTHREADS - 1) / NTHREADS; it++) {
            int i = it * NTHREADS + tid;
            if (i < BFRAG_FLOATS / 4) dst[i] = src[i];
        }
        if (tid < NDIM) bs[tid] = g_bias[tid];
    }

    // ---- fill A into fragment-packed layout ----
    // item = ((t*8 + qrf)*10 + kt); 1280 items, 5 per thread.
    #pragma unroll
    for (int it = 0; it < 5; it++) {
        int item = it * NTHREADS + tid;
        int kt  = item % 10;
        int g2  = item / 10;
        int qrf = g2 & 7;
        int t   = g2 >> 3;            // 0..15
        int r0g = row0 + t * 16 + qrf;
        const float* p0;
        const float* p1;
        if (kt < 8) {
            p0 = x + (size_t)r0g * IN_SZ + kt * 8;
            p1 = p0 + 8 * IN_SZ;
        } else {
            p0 = h_prev + (size_t)r0g * HID + (kt - 8) * 8;
            p1 = p0 + 8 * HID;
        }
        float4 f0a = *reinterpret_cast<const float4*>(p0);
        float4 f0b = *reinterpret_cast<const float4*>(p0 + 4);
        float4 f1a = *reinterpret_cast<const float4*>(p1);
        float4 f1b = *reinterpret_cast<const float4*>(p1 + 4);
        float a0[4] = {f0a.x, f0a.y, f0a.z, f0a.w};   // (r,   k..k+3)
        float a1[4] = {f1a.x, f1a.y, f1a.z, f1a.w};   // (r+8, k..k+3)
        float a2[4] = {f0b.x, f0b.y, f0b.z, f0b.w};   // (r,   k+4..k+7)
        float a3[4] = {f1b.x, f1b.y, f1b.z, f1b.w};   // (r+8, k+4..k+7)
        uint32_t* dstbase = As + t * A_TILE_FLOATS + kt * 128 + qrf * 16;
        #pragma unroll
        for (int q = 0; q < 4; q++) {
            int phys = (q + qrf + kt) & 3;
            uint4 v;
            v.x = f2tf32(a0[q]);
            v.y = f2tf32(a1[q]);
            v.z = f2tf32(a2[q]);
            v.w = f2tf32(a3[q]);
            *reinterpret_cast<uint4*>(dstbase + phys * 4) = v;
        }
    }
    __syncthreads();

    // ---- GEMM: per warp 32 rows (2 m-tiles) x 80 cols ----
    // per kt: 2 A LDS.128 + 5 B LDS.128 + 20 HMMA
    float acc[2][10][4];
    #pragma unroll
    for (int mt = 0; mt < 2; mt++)
        #pragma unroll
        for (int nt = 0; nt < 10; nt++)
            #pragma unroll
            for (int c = 0; c < 4; c++) acc[mt][nt][c] = 0.0f;

    const uint32_t* Aw0 = As + (warp * 2 + 0) * A_TILE_FLOATS + qr * 16;
    const uint32_t* Aw1 = As + (warp * 2 + 1) * A_TILE_FLOATS + qr * 16;
    const uint4* Bs4 = reinterpret_cast<const uint4*>(Bs) + lane;

    #pragma unroll
    for (int kt = 0; kt < 10; kt++) {
        int ph = ((qc + qr + kt) & 3) << 2;
        uint4 av0 = *reinterpret_cast<const uint4*>(Aw0 + kt * 128 + ph);
        uint4 av1 = *reinterpret_cast<const uint4*>(Aw1 + kt * 128 + ph);
        uint32_t a0[4] = {av0.x, av0.y, av0.z, av0.w};
        uint32_t a1[4] = {av1.x, av1.y, av1.z, av1.w};
        #pragma unroll
        for (int np = 0; np < 5; np++) {
            uint4 bv = Bs4[(kt * 5 + np) * 32];
            mma_tf32(acc[0][2 * np],     a0, bv.x, bv.y);
            mma_tf32(acc[0][2 * np + 1], a0, bv.z, bv.w);
            mma_tf32(acc[1][2 * np],     a1, bv.x, bv.y);
            mma_tf32(acc[1][2 * np + 1], a1, bv.z, bv.w);
        }
    }

    // ---- epilogue operands (after MMA to keep loop reg pressure low) ----
    const int mbase = warp * 32;
    float2 cpv[2][2][2];
    float  dtv[2][2];
    #pragma unroll
    for (int mt = 0; mt < 2; mt++)
        #pragma unroll
        for (int rs = 0; rs < 2; rs++) {
            size_t row = (size_t)row0 + mbase + mt * 16 + rs * 8 + qr;
            dtv[mt][rs] = delta_t[row];
            #pragma unroll
            for (int jh = 0; jh < 2; jh++) {
                int j0 = jh * 8 + 2 * qc;
                cpv[mt][rs][jh] = *reinterpret_cast<const float2*>(c_prev + row * HID + j0);
            }
        }

    // ---- epilogue: z col C = g*16 + jh*8 + 2*qc + b <- acc[mt][2*g + jh][rs*2 + b] ----
    #pragma unroll
    for (int mt = 0; mt < 2; mt++) {
        #pragma unroll
        for (int rs = 0; rs < 2; rs++) {
            size_t row = (size_t)row0 + mbase + mt * 16 + rs * 8 + qr;
            float dt = dtv[mt][rs];
            #pragma unroll
            for (int jh = 0; jh < 2; jh++) {
                float2 cp = cpv[mt][rs][jh];
                float cpin[2] = {cp.x, cp.y};
                float h2[2], c2[2];
                #pragma unroll
                for (int b = 0; b < 2; b++) {
                    int C = jh * 8 + 2 * qc + b;
                    float zi = acc[mt][0 + jh][rs * 2 + b] + bs[C];
                    float zf = acc[mt][2 + jh][rs * 2 + b] + bs[16 + C];
                    float zo = acc[mt][4 + jh][rs * 2 + b] + bs[32 + C];
                    float zc = acc[mt][6 + jh][rs * 2 + b] + bs[48 + C];
                    float zd = acc[mt][8 + jh][rs * 2 + b] + bs[64 + C];
                    float ig = tanh_fast(zi);
                    float fg = tanh_fast(zf);
                    float og = tanh_fast(zo);
                    float ct = tanh_fast(zc);
                    float decay = softplus_fast(zd);
                    float cdec = cpin[b] * __expf(-decay * dt);
                    float cn = fg * cdec + ig * ct;
                    c2[b] = cn;
                    h2[b] = og * tanh_fast(cn);
                }
                int j0 = jh * 8 + 2 * qc;
                *reinterpret_cast<float2*>(out_h + row * HID + j0) = make_float2(h2[0], h2[1]);
                *reinterpret_cast<float2*>(out_c + row * HID + j0) = make_float2(c2[0], c2[1]);
            }
        }
    }
}

extern "C" void kernel_launch(void* const* d_in, const int* in_sizes, int n_in,
                              void* d_out, int out_size) {
    const float* x      = (const float*)d_in[0];
    const float* h_prev = (const float*)d_in[1];
    const float* c_prev = (const float*)d_in[2];
    const float* dt     = (const float*)d_in[3];
    const float* W_i = (const float*)d_in[4];
    const float* b_i = (const float*)d_in[5];
    const float* W_f = (const float*)d_in[6];
    const float* b_f = (const float*)d_in[7];
    const float* W_o = (const float*)d_in[8];
    const float* b_o = (const float*)d_in[9];
    const float* W_c = (const float*)d_in[10];
    const float* b_c = (const float*)d_in[11];
    const float* W_d = (const float*)d_in[12];
    const float* b_d = (const float*)d_in[13];

    float* out_h = (float*)d_out;
    float* out_c = out_h + (size_t)out_size / 2;  // (h_next, c_next) concatenated

    cudaFuncSetAttribute(ctlstm_kernel, cudaFuncAttributeMaxDynamicSharedMemorySize, SMEM_BYTES);

    // one-time weight fragment packing (graph-capturable, ordered before main)
    prep_kernel<<<(BFRAG_FLOATS + NDIM + 255) / 256, 256>>>(
        W_i, b_i, W_f, b_f, W_o, b_o, W_c, b_c, W_d, b_d);

    dim3 grid(BATCH_N / TILE_M);
    ctlstm_kernel<<<grid, NTHREADS, SMEM_BYTES>>>(
        x, h_prev, c_prev, dt, out_h, out_c);
}

// round 10
// speedup vs baseline: 1.0525x; 1.0525x over previous
#include <cuda_runtime.h>
#include <cstdint>

// ---------------- problem constants ----------------
#define BATCH_N   1048576
#define IN_SZ     64
#define HID       16
#define KDIM      80          // IN_SZ + HID
#define NDIM      80          // 5 * HID
#define TILE_M    128
#define NTHREADS  256

// A smem: fragment-packed. Per 16-row tile: [kt=10][qr=8][phys qc=4][4 floats]
#define A_TILE_FLOATS 1280
#define N_TILES       (TILE_M / 16)              // 8
#define A_FLOATS      (N_TILES * A_TILE_FLOATS)  // 10240
// B fragments in smem: [kt=10][np=5][lane=32][4] = 6400
#define BFRAG_FLOATS  6400
#define SMEM_FLOATS   (A_FLOATS + BFRAG_FLOATS + NDIM)
#define SMEM_BYTES    (SMEM_FLOATS * 4)          // 66880 (~65.3 KB) -> 3 CTAs/SM

__device__ uint32_t g_Bfrag[BFRAG_FLOATS];
__device__ float    g_bias[NDIM];

static __device__ __forceinline__ uint32_t f2tf32(float f) {
    uint32_t u;
    asm("cvt.rna.tf32.f32 %0, %1;" : "=r"(u) : "f"(f));
    return u;
}

static __device__ __forceinline__ void mma_tf32(float* c, const uint32_t* a,
                                                uint32_t b0, uint32_t b1) {
    asm volatile(
        "mma.sync.aligned.m16n8k8.row.col.f32.tf32.tf32.f32 "
        "{%0,%1,%2,%3}, {%4,%5,%6,%7}, {%8,%9}, {%0,%1,%2,%3};"
        : "+f"(c[0]), "+f"(c[1]), "+f"(c[2]), "+f"(c[3])
        : "r"(a[0]), "r"(a[1]), "r"(a[2]), "r"(a[3]), "r"(b0), "r"(b1));
}

// single-instruction tanh (MUFU.TANH, sm_75+)
static __device__ __forceinline__ float tanh_approx(float x) {
    float y;
    asm("tanh.approx.f32 %0, %1;" : "=f"(y) : "f"(x));
    return y;
}
static __device__ __forceinline__ float softplus_fast(float x) {
    return fmaxf(x, 0.0f) + __logf(1.0f + __expf(-fabsf(x)));
}

// ---------------- prep: pack W into per-lane mma B-fragments + bias ----------------
// g_Bfrag index i = ((kt*5 + np)*32 + lane)*4 + slot
//   lane = qr*4 + qc ; nt = 2*np + (slot>>1) ; pos = slot&1
//   value = tf32( W[k = kt*8 + qc + 4*pos][n = nt*8 + qr] )
__global__ void prep_kernel(
    const float* __restrict__ W_i, const float* __restrict__ b_i,
    const float* __restrict__ W_f, const float* __restrict__ b_f,
    const float* __restrict__ W_o, const float* __restrict__ b_o,
    const float* __restrict__ W_c, const float* __restrict__ b_c,
    const float* __restrict__ W_d, const float* __restrict__ b_d)
{
    int i = blockIdx.x * blockDim.x + threadIdx.x;
    if (i < BFRAG_FLOATS) {
        int slot = i & 3;
        int lane = (i >> 2) & 31;
        int rest = i >> 7;            // 0..49
        int np = rest % 5;
        int kt = rest / 5;
        int qr = lane >> 2;
        int qc = lane & 3;
        int nt = 2 * np + (slot >> 1);
        int pos = slot & 1;
        int k = kt * 8 + qc + 4 * pos;
        int n = nt * 8 + qr;
        int g = n >> 4, c = n & 15;
        const float* W = (g == 0) ? W_i : (g == 1) ? W_f : (g == 2) ? W_o
                       : (g == 3) ? W_c : W_d;
        g_Bfrag[i] = f2tf32(W[k * HID + c]);
    } else if (i < BFRAG_FLOATS + NDIM) {
        int n = i - BFRAG_FLOATS;
        int g = n >> 4, c = n & 15;
        const float* B = (g == 0) ? b_i : (g == 1) ? b_f : (g == 2) ? b_o
                       : (g == 3) ? b_c : b_d;
        g_bias[n] = B[c];
    }
}

__global__ void __launch_bounds__(NTHREADS, 3) ctlstm_kernel(
    const float* __restrict__ x,
    const float* __restrict__ h_prev,
    const float* __restrict__ c_prev,
    const float* __restrict__ delta_t,
    float* __restrict__ out_h, float* __restrict__ out_c)
{
    extern __shared__ uint32_t smem[];
    uint32_t* As = smem;                                        // fragment-packed A
    uint32_t* Bs = smem + A_FLOATS;                             // fragment-packed B
    float*    bs = reinterpret_cast<float*>(smem + A_FLOATS + BFRAG_FLOATS); // bias

    const int tid  = threadIdx.x;
    const int warp = tid >> 5;
    const int lane = tid & 31;
    const int qr   = lane >> 2;   // 0..7
    const int qc   = lane & 3;    // 0..3
    const int row0 = blockIdx.x * TILE_M;

    // ---- B fragments + bias: coalesced copy from precomputed globals (L2-hot) ----
    {
        const uint4* src = reinterpret_cast<const uint4*>(g_Bfrag);
        uint4* dst = reinterpret_cast<uint4*>(Bs);
        #pragma unroll
        for (int it = 0; it < 7; it++) {
            int i = it * NTHREADS + tid;
            if (i < BFRAG_FLOATS / 4) dst[i] = src[i];
        }
        if (tid < NDIM) bs[tid] = g_bias[tid];
    }

    // ---- fill A into fragment-packed layout ----
    // item = ((t*8 + qrf)*10 + kt); 640 items, <=3 per thread.
    #pragma unroll
    for (int it = 0; it < 3; it++) {
        int item = it * NTHREADS + tid;
        if (item < 640) {
            int kt  = item % 10;
            int g2  = item / 10;
            int qrf = g2 & 7;
            int t   = g2 >> 3;            // 0..7
            int r0g = row0 + t * 16 + qrf;
            const float* p0;
            const float* p1;
            if (kt < 8) {
                p0 = x + (size_t)r0g * IN_SZ + kt * 8;
                p1 = p0 + 8 * IN_SZ;
            } else {
                p0 = h_prev + (size_t)r0g * HID + (kt - 8) * 8;
                p1 = p0 + 8 * HID;
            }
            float4 f0a = *reinterpret_cast<const float4*>(p0);
            float4 f0b = *reinterpret_cast<const float4*>(p0 + 4);
            float4 f1a = *reinterpret_cast<const float4*>(p1);
            float4 f1b = *reinterpret_cast<const float4*>(p1 + 4);
            float a0[4] = {f0a.x, f0a.y, f0a.z, f0a.w};   // (r,   k..k+3)
            float a1[4] = {f1a.x, f1a.y, f1a.z, f1a.w};   // (r+8, k..k+3)
            float a2[4] = {f0b.x, f0b.y, f0b.z, f0b.w};   // (r,   k+4..k+7)
            float a3[4] = {f1b.x, f1b.y, f1b.z, f1b.w};   // (r+8, k+4..k+7)
            uint32_t* dstbase = As + t * A_TILE_FLOATS + kt * 128 + qrf * 16;
            #pragma unroll
            for (int q = 0; q < 4; q++) {
                int phys = (q + qrf + kt) & 3;
                uint4 v;
                v.x = f2tf32(a0[q]);
                v.y = f2tf32(a1[q]);
                v.z = f2tf32(a2[q]);
                v.w = f2tf32(a3[q]);
                *reinterpret_cast<uint4*>(dstbase + phys * 4) = v;
            }
        }
    }
    __syncthreads();

    // ---- GEMM: per warp 16 rows x 80 cols; per kt: 1 A LDS.128 + 5 B LDS.128 + 10 HMMA
    float acc[10][4];
    #pragma unroll
    for (int nt = 0; nt < 10; nt++)
        #pragma unroll
        for (int c = 0; c < 4; c++) acc[nt][c] = 0.0f;

    const uint32_t* Aw = As + warp * A_TILE_FLOATS + qr * 16;
    const uint4* Bs4 = reinterpret_cast<const uint4*>(Bs) + lane;

    #pragma unroll
    for (int kt = 0; kt < 10; kt++) {
        uint4 av = *reinterpret_cast<const uint4*>(Aw + kt * 128 + (((qc + qr + kt) & 3) << 2));
        uint32_t a[4] = {av.x, av.y, av.z, av.w};
        #pragma unroll
        for (int np = 0; np < 5; np++) {
            uint4 bv = Bs4[(kt * 5 + np) * 32];
            mma_tf32(acc[2 * np],     a, bv.x, bv.y);
            mma_tf32(acc[2 * np + 1], a, bv.z, bv.w);
        }
    }

    // ---- epilogue operands ----
    const int mbase = warp * 16;
    float2 cpv[2][2];
    float  dtv[2];
    #pragma unroll
    for (int rs = 0; rs < 2; rs++) {
        size_t row = (size_t)row0 + mbase + rs * 8 + qr;
        dtv[rs] = delta_t[row];
        #pragma unroll
        for (int jh = 0; jh < 2; jh++) {
            int j0 = jh * 8 + 2 * qc;
            cpv[rs][jh] = *reinterpret_cast<const float2*>(c_prev + row * HID + j0);
        }
    }

    // ---- epilogue: z col C = g*16 + jh*8 + 2*qc + b <- acc[2*g + jh][rs*2 + b] ----
    #pragma unroll
    for (int rs = 0; rs < 2; rs++) {
        size_t row = (size_t)row0 + mbase + rs * 8 + qr;
        float dt = dtv[rs];
        #pragma unroll
        for (int jh = 0; jh < 2; jh++) {
            float2 cp = cpv[rs][jh];
            float cpin[2] = {cp.x, cp.y};
            float h2[2], c2[2];
            #pragma unroll
            for (int b = 0; b < 2; b++) {
                int C = jh * 8 + 2 * qc + b;
                float zi = acc[0 + jh][rs * 2 + b] + bs[C];
                float zf = acc[2 + jh][rs * 2 + b] + bs[16 + C];
                float zo = acc[4 + jh][rs * 2 + b] + bs[32 + C];
                float zc = acc[6 + jh][rs * 2 + b] + bs[48 + C];
                float zd = acc[8 + jh][rs * 2 + b] + bs[64 + C];
                float ig = tanh_approx(zi);
                float fg = tanh_approx(zf);
                float og = tanh_approx(zo);
                float ct = tanh_approx(zc);
                float decay = softplus_fast(zd);
                float cdec = cpin[b] * __expf(-decay * dt);
                float cn = fg * cdec + ig * ct;
                c2[b] = cn;
                h2[b] = og * tanh_approx(cn);
            }
            int j0 = jh * 8 + 2 * qc;
            *reinterpret_cast<float2*>(out_h + row * HID + j0) = make_float2(h2[0], h2[1]);
            *reinterpret_cast<float2*>(out_c + row * HID + j0) = make_float2(c2[0], c2[1]);
        }
    }
}

extern "C" void kernel_launch(void* const* d_in, const int* in_sizes, int n_in,
                              void* d_out, int out_size) {
    const float* x      = (const float*)d_in[0];
    const float* h_prev = (const float*)d_in[1];
    const float* c_prev = (const float*)d_in[2];
    const float* dt     = (const float*)d_in[3];
    const float* W_i = (const float*)d_in[4];
    const float* b_i = (const float*)d_in[5];
    const float* W_f = (const float*)d_in[6];
    const float* b_f = (const float*)d_in[7];
    const float* W_o = (const float*)d_in[8];
    const float* b_o = (const float*)d_in[9];
    const float* W_c = (const float*)d_in[10];
    const float* b_c = (const float*)d_in[11];
    const float* W_d = (const float*)d_in[12];
    const float* b_d = (const float*)d_in[13];

    float* out_h = (float*)d_out;
    float* out_c = out_h + (size_t)out_size / 2;  // (h_next, c_next) concatenated

    cudaFuncSetAttribute(ctlstm_kernel, cudaFuncAttributeMaxDynamicSharedMemorySize, SMEM_BYTES);

    // one-time weight fragment packing (graph-capturable, ordered before main)
    prep_kernel<<<(BFRAG_FLOATS + NDIM + 255) / 256, 256>>>(
        W_i, b_i, W_f, b_f, W_o, b_o, W_c, b_c, W_d, b_d);

    dim3 grid(BATCH_N / TILE_M);
    ctlstm_kernel<<<grid, NTHREADS, SMEM_BYTES>>>(
        x, h_prev, c_prev, dt, out_h, out_c);
}

// round 11
// speedup vs baseline: 1.2447x; 1.1826x over previous
#include <cuda_runtime.h>
#include <cstdint>

// ---------------- problem constants ----------------
#define BATCH_N   1048576
#define IN_SZ     64
#define HID       16
#define KDIM      80          // IN_SZ + HID
#define NDIM      80          // 5 * HID
#define TILE_M    128
#define NTHREADS  256

// smem strides (in floats) chosen for conflict-free mma fragment LDS
#define SA 84                 // A row stride: banks (20*qr + qc) % 32 all distinct
#define SB 88                 // B row stride: banks (24*qc + qr) % 32 all distinct

#define A_FLOATS (TILE_M * SA)        // 10752
#define B_FLOATS (KDIM * SB)          // 7040
#define SMEM_FLOATS (A_FLOATS + B_FLOATS + NDIM)
#define SMEM_BYTES  (SMEM_FLOATS * 4) // 71488

// ---------------- precomputed weights (written by prep kernel) ----------------
__device__ uint32_t g_Bp[B_FLOATS];    // tf32 W as [k][n], stride SB
__device__ float    g_bias[NDIM];

static __device__ __forceinline__ uint32_t f2tf32(float f) {
    uint32_t u;
    asm("cvt.rna.tf32.f32 %0, %1;" : "=r"(u) : "f"(f));
    return u;
}

static __device__ __forceinline__ void mma_tf32(float* c, const uint32_t* a,
                                                uint32_t b0, uint32_t b1) {
    asm volatile(
        "mma.sync.aligned.m16n8k8.row.col.f32.tf32.tf32.f32 "
        "{%0,%1,%2,%3}, {%4,%5,%6,%7}, {%8,%9}, {%0,%1,%2,%3};"
        : "+f"(c[0]), "+f"(c[1]), "+f"(c[2]), "+f"(c[3])
        : "r"(a[0]), "r"(a[1]), "r"(a[2]), "r"(a[3]), "r"(b0), "r"(b1));
}

// single-instruction tanh (MUFU.TANH, sm_75+) — validated in R10: rel_err unchanged
static __device__ __forceinline__ float tanh_approx(float x) {
    float y;
    asm("tanh.approx.f32 %0, %1;" : "=f"(y) : "f"(x));
    return y;
}
static __device__ __forceinline__ float softplus_fast(float x) {
    return fmaxf(x, 0.0f) + __logf(1.0f + __expf(-fabsf(x)));
}

// ---------------- prep: pack W -> tf32 [k][n] stride SB, bias ----------------
__global__ void prep_kernel(
    const float* __restrict__ W_i, const float* __restrict__ b_i,
    const float* __restrict__ W_f, const float* __restrict__ b_f,
    const float* __restrict__ W_o, const float* __restrict__ b_o,
    const float* __restrict__ W_c, const float* __restrict__ b_c,
    const float* __restrict__ W_d, const float* __restrict__ b_d)
{
    int idx = blockIdx.x * blockDim.x + threadIdx.x;
    if (idx < NDIM * KDIM) {
        int k = idx / NDIM;
        int n = idx - k * NDIM;
        int g = n >> 4, c = n & 15;
        const float* W = (g == 0) ? W_i : (g == 1) ? W_f : (g == 2) ? W_o
                       : (g == 3) ? W_c : W_d;
        g_Bp[k * SB + n] = f2tf32(W[k * HID + c]);
    } else if (idx < NDIM * KDIM + NDIM) {
        int n = idx - NDIM * KDIM;
        int g = n >> 4, c = n & 15;
        const float* B = (g == 0) ? b_i : (g == 1) ? b_f : (g == 2) ? b_o
                       : (g == 3) ? b_c : b_d;
        g_bias[n] = B[c];
    }
    // zero the pad columns once so the main kernel's vector copy is defined
    if (idx < KDIM) {
        #pragma unroll
        for (int p = NDIM; p < SB; p++) g_Bp[idx * SB + p] = 0u;
    }
}

__global__ void __launch_bounds__(NTHREADS, 3) ctlstm_kernel(
    const float* __restrict__ x,
    const float* __restrict__ h_prev,
    const float* __restrict__ c_prev,
    const float* __restrict__ delta_t,
    float* __restrict__ out_h, float* __restrict__ out_c)
{
    extern __shared__ uint32_t smem[];
    uint32_t* As = smem;                    // [128][SA] tf32
    uint32_t* Bs = smem + A_FLOATS;         // [80][SB]  tf32 (W as [k][n])
    float*    bs = reinterpret_cast<float*>(smem + A_FLOATS + B_FLOATS); // bias[80]

    const int tid  = threadIdx.x;
    const int warp = tid >> 5;
    const int lane = tid & 31;
    const int qr   = lane >> 2;   // 0..7
    const int qc   = lane & 3;    // 0..3
    const int row0 = blockIdx.x * TILE_M;

    // ---- copy B + bias from precomputed globals (coalesced, L2-hot) ----
    {
        const uint4* src = reinterpret_cast<const uint4*>(g_Bp);
        uint4* dst = reinterpret_cast<uint4*>(Bs);
        #pragma unroll
        for (int it = 0; it < B_FLOATS / 4 / NTHREADS + 1; it++) {
            int i = it * NTHREADS + tid;
            if (i < B_FLOATS / 4) dst[i] = src[i];
        }
        if (tid < NDIM) bs[tid] = g_bias[tid];
    }

    // ---- fill A: x part [128 rows, cols 0..63] ----
    #pragma unroll
    for (int it = 0; it < (TILE_M * (IN_SZ / 4)) / NTHREADS; it++) {  // 8 iters
        int idx = it * NTHREADS + tid;
        int m = idx >> 4;
        int c4 = idx & 15;
        float4 v = *reinterpret_cast<const float4*>(x + (size_t)(row0 + m) * IN_SZ + c4 * 4);
        uint4 t;
        t.x = f2tf32(v.x); t.y = f2tf32(v.y); t.z = f2tf32(v.z); t.w = f2tf32(v.w);
        *reinterpret_cast<uint4*>(As + m * SA + c4 * 4) = t;
    }
    // ---- fill A: h part [128 rows, cols 64..79] ----
    #pragma unroll
    for (int it = 0; it < (TILE_M * (HID / 4)) / NTHREADS; it++) {    // 2 iters
        int idx = it * NTHREADS + tid;
        int m = idx >> 2;
        int c4 = idx & 3;
        float4 v = *reinterpret_cast<const float4*>(h_prev + (size_t)(row0 + m) * HID + c4 * 4);
        uint4 t;
        t.x = f2tf32(v.x); t.y = f2tf32(v.y); t.z = f2tf32(v.z); t.w = f2tf32(v.w);
        *reinterpret_cast<uint4*>(As + m * SA + IN_SZ + c4 * 4) = t;
    }

    // ---- prefetch epilogue operands early (overlap with MMA) ----
    // Per thread: rows = row0 + warp*16 + rs*8 + qr (rs in {0,1})
    // cols j0 = jh*8 + 2*qc (jh in {0,1}), 2 consecutive floats each
    float2 cpv[2][2];
    float  dtv[2];
    #pragma unroll
    for (int rs = 0; rs < 2; rs++) {
        size_t row = (size_t)row0 + warp * 16 + rs * 8 + qr;
        dtv[rs] = delta_t[row];
        #pragma unroll
        for (int jh = 0; jh < 2; jh++) {
            int j0 = jh * 8 + 2 * qc;
            cpv[rs][jh] = *reinterpret_cast<const float2*>(c_prev + row * HID + j0);
        }
    }

    __syncthreads();

    // ---- GEMM: per warp 1 m-tile(16 rows) x 10 n-tiles x 10 k-tiles of m16n8k8 ----
    float acc[10][4];
    #pragma unroll
    for (int nt = 0; nt < 10; nt++)
        #pragma unroll
        for (int c = 0; c < 4; c++) acc[nt][c] = 0.0f;

    const int mbase = warp * 16;
    #pragma unroll
    for (int kt = 0; kt < 10; kt++) {
        uint32_t a[4];
        {
            int r = mbase + qr;
            int k = kt * 8 + qc;
            a[0] = As[r * SA + k];
            a[1] = As[(r + 8) * SA + k];
            a[2] = As[r * SA + k + 4];
            a[3] = As[(r + 8) * SA + k + 4];
        }
        #pragma unroll
        for (int nt = 0; nt < 10; nt++) {
            int n = nt * 8 + qr;
            uint32_t b0 = Bs[(kt * 8 + qc) * SB + n];
            uint32_t b1 = Bs[(kt * 8 + qc + 4) * SB + n];
            mma_tf32(acc[nt], a, b0, b1);
        }
    }

    // ---- epilogue ----
    // z col C = g*16 + jh*8 + 2*qc + b  maps to acc[2*g + jh][rs*2 + b]
    #pragma unroll
    for (int rs = 0; rs < 2; rs++) {
        size_t row = (size_t)row0 + mbase + rs * 8 + qr;
        float dt = dtv[rs];
        #pragma unroll
        for (int jh = 0; jh < 2; jh++) {
            float2 cp = cpv[rs][jh];
            float cpin[2] = {cp.x, cp.y};
            float h2[2], c2[2];
            #pragma unroll
            for (int b = 0; b < 2; b++) {
                int C = jh * 8 + 2 * qc + b;
                float zi = acc[0 + jh][rs * 2 + b] + bs[C];
                float zf = acc[2 + jh][rs * 2 + b] + bs[16 + C];
                float zo = acc[4 + jh][rs * 2 + b] + bs[32 + C];
                float zc = acc[6 + jh][rs * 2 + b] + bs[48 + C];
                float zd = acc[8 + jh][rs * 2 + b] + bs[64 + C];
                float ig = tanh_approx(zi);
                float fg = tanh_approx(zf);
                float og = tanh_approx(zo);
                float ct = tanh_approx(zc);
                float decay = softplus_fast(zd);
                float cdec = cpin[b] * __expf(-decay * dt);
                float cn = fg * cdec + ig * ct;
                c2[b] = cn;
                h2[b] = og * tanh_approx(cn);
            }
            int j0 = jh * 8 + 2 * qc;
            *reinterpret_cast<float2*>(out_h + row * HID + j0) = make_float2(h2[0], h2[1]);
            *reinterpret_cast<float2*>(out_c + row * HID + j0) = make_float2(c2[0], c2[1]);
        }
    }
}

extern "C" void kernel_launch(void* const* d_in, const int* in_sizes, int n_in,
                              void* d_out, int out_size) {
    const float* x      = (const float*)d_in[0];
    const float* h_prev = (const float*)d_in[1];
    const float* c_prev = (const float*)d_in[2];
    const float* dt     = (const float*)d_in[3];
    const float* W_i = (const float*)d_in[4];
    const float* b_i = (const float*)d_in[5];
    const float* W_f = (const float*)d_in[6];
    const float* b_f = (const float*)d_in[7];
    const float* W_o = (const float*)d_in[8];
    const float* b_o = (const float*)d_in[9];
    const float* W_c = (const float*)d_in[10];
    const float* b_c = (const float*)d_in[11];
    const float* W_d = (const float*)d_in[12];
    const float* b_d = (const float*)d_in[13];

    float* out_h = (float*)d_out;
    float* out_c = out_h + (size_t)out_size / 2;  // (h_next, c_next) concatenated

    cudaFuncSetAttribute(ctlstm_kernel, cudaFuncAttributeMaxDynamicSharedMemorySize, SMEM_BYTES);

    // one-time weight packing (cheap; graph-capturable, ordered before main)
    prep_kernel<<<(NDIM * KDIM + NDIM + 255) / 256, 256>>>(
        W_i, b_i, W_f, b_f, W_o, b_o, W_c, b_c, W_d, b_d);

    dim3 grid(BATCH_N / TILE_M);
    ctlstm_kernel<<<grid, NTHREADS, SMEM_BYTES>>>(
        x, h_prev, c_prev, dt, out_h, out_c);
}

// round 12
// speedup vs baseline: 1.2563x; 1.0094x over previous
#include <cuda_runtime.h>
#include <cstdint>

// ---------------- problem constants ----------------
#define BATCH_N   1048576
#define IN_SZ     64
#define HID       16
#define KDIM      80          // IN_SZ + HID
#define NDIM      80          // 5 * HID
#define TILE_M    128
#define NTHREADS  256

// smem strides (in floats) chosen for conflict-free mma fragment LDS
#define SA 84                 // A: bank (20*r + qc) % 32 all distinct over a warp
#define SB 88                 // B: bank (24*qc + qr [+8*(nt%4)]) % 32 all distinct

#define A_FLOATS (TILE_M * SA)        // 10752
#define B_FLOATS (KDIM * SB)          // 7040
#define SMEM_FLOATS (A_FLOATS + B_FLOATS + NDIM)
#define SMEM_BYTES  (SMEM_FLOATS * 4) // 71488 -> 3 CTAs/SM

// ---------------- precomputed weights (written by prep kernel) ----------------
__device__ uint32_t g_Bp[B_FLOATS];    // tf32 W as [k][n], stride SB
__device__ float    g_bias[NDIM];

static __device__ __forceinline__ uint32_t f2tf32(float f) {
    uint32_t u;
    asm("cvt.rna.tf32.f32 %0, %1;" : "=r"(u) : "f"(f));
    return u;
}

static __device__ __forceinline__ void mma_tf32(float* c, const uint32_t* a,
                                                uint32_t b0, uint32_t b1) {
    asm volatile(
        "mma.sync.aligned.m16n8k8.row.col.f32.tf32.tf32.f32 "
        "{%0,%1,%2,%3}, {%4,%5,%6,%7}, {%8,%9}, {%0,%1,%2,%3};"
        : "+f"(c[0]), "+f"(c[1]), "+f"(c[2]), "+f"(c[3])
        : "r"(a[0]), "r"(a[1]), "r"(a[2]), "r"(a[3]), "r"(b0), "r"(b1));
}

// single-instruction tanh (MUFU.TANH) — validated: rel_err unchanged vs exact
static __device__ __forceinline__ float tanh_approx(float x) {
    float y;
    asm("tanh.approx.f32 %0, %1;" : "=f"(y) : "f"(x));
    return y;
}
static __device__ __forceinline__ float softplus_fast(float x) {
    return fmaxf(x, 0.0f) + __logf(1.0f + __expf(-fabsf(x)));
}

// ---------------- prep: pack W -> tf32 [k][n] stride SB, bias ----------------
__global__ void prep_kernel(
    const float* __restrict__ W_i, const float* __restrict__ b_i,
    const float* __restrict__ W_f, const float* __restrict__ b_f,
    const float* __restrict__ W_o, const float* __restrict__ b_o,
    const float* __restrict__ W_c, const float* __restrict__ b_c,
    const float* __restrict__ W_d, const float* __restrict__ b_d)
{
    int idx = blockIdx.x * blockDim.x + threadIdx.x;
    if (idx < NDIM * KDIM) {
        int k = idx / NDIM;
        int n = idx - k * NDIM;
        int g = n >> 4, c = n & 15;
        const float* W = (g == 0) ? W_i : (g == 1) ? W_f : (g == 2) ? W_o
                       : (g == 3) ? W_c : W_d;
        g_Bp[k * SB + n] = f2tf32(W[k * HID + c]);
    } else if (idx < NDIM * KDIM + NDIM) {
        int n = idx - NDIM * KDIM;
        int g = n >> 4, c = n & 15;
        const float* B = (g == 0) ? b_i : (g == 1) ? b_f : (g == 2) ? b_o
                       : (g == 3) ? b_c : b_d;
        g_bias[n] = B[c];
    }
    // zero the pad columns once so the main kernel's vector copy is defined
    if (idx < KDIM) {
        #pragma unroll
        for (int p = NDIM; p < SB; p++) g_Bp[idx * SB + p] = 0u;
    }
}

__global__ void __launch_bounds__(NTHREADS, 3) ctlstm_kernel(
    const float* __restrict__ x,
    const float* __restrict__ h_prev,
    const float* __restrict__ c_prev,
    const float* __restrict__ delta_t,
    float* __restrict__ out_h, float* __restrict__ out_c)
{
    extern __shared__ uint32_t smem[];
    uint32_t* As = smem;                    // [128][SA] tf32
    uint32_t* Bs = smem + A_FLOATS;         // [80][SB]  tf32 (W as [k][n])
    float*    bs = reinterpret_cast<float*>(smem + A_FLOATS + B_FLOATS); // bias[80]

    const int tid  = threadIdx.x;
    const int warp = tid >> 5;
    const int lane = tid & 31;
    const int qr   = lane >> 2;   // 0..7
    const int qc   = lane & 3;    // 0..3
    const int row0 = blockIdx.x * TILE_M;

    // N-split warp pairing: rg picks the 32-row group, nh picks column half
    const int rg = warp & 3;      // row group: rows rg*32 .. rg*32+31
    const int nh = warp >> 2;     // 0: cols 0-7 of each gate, 1: cols 8-15

    // ---- copy B + bias from precomputed globals (coalesced, L2-hot) ----
    {
        const uint4* src = reinterpret_cast<const uint4*>(g_Bp);
        uint4* dst = reinterpret_cast<uint4*>(Bs);
        #pragma unroll
        for (int it = 0; it < B_FLOATS / 4 / NTHREADS + 1; it++) {
            int i = it * NTHREADS + tid;
            if (i < B_FLOATS / 4) dst[i] = src[i];
        }
        if (tid < NDIM) bs[tid] = g_bias[tid];
    }

    // ---- fill A: x part [128 rows, cols 0..63] ----
    #pragma unroll
    for (int it = 0; it < (TILE_M * (IN_SZ / 4)) / NTHREADS; it++) {  // 8 iters
        int idx = it * NTHREADS + tid;
        int m = idx >> 4;
        int c4 = idx & 15;
        float4 v = *reinterpret_cast<const float4*>(x + (size_t)(row0 + m) * IN_SZ + c4 * 4);
        uint4 t;
        t.x = f2tf32(v.x); t.y = f2tf32(v.y); t.z = f2tf32(v.z); t.w = f2tf32(v.w);
        *reinterpret_cast<uint4*>(As + m * SA + c4 * 4) = t;
    }
    // ---- fill A: h part [128 rows, cols 64..79] ----
    #pragma unroll
    for (int it = 0; it < (TILE_M * (HID / 4)) / NTHREADS; it++) {    // 2 iters
        int idx = it * NTHREADS + tid;
        int m = idx >> 2;
        int c4 = idx & 3;
        float4 v = *reinterpret_cast<const float4*>(h_prev + (size_t)(row0 + m) * HID + c4 * 4);
        uint4 t;
        t.x = f2tf32(v.x); t.y = f2tf32(v.y); t.z = f2tf32(v.z); t.w = f2tf32(v.w);
        *reinterpret_cast<uint4*>(As + m * SA + IN_SZ + c4 * 4) = t;
    }

    // ---- prefetch epilogue operands early (overlap with MMA) ----
    // Per thread: rows = row0 + rg*32 + mt*16 + rs*8 + qr; cols j0 = nh*8 + 2*qc
    const int mbase = rg * 32;
    const int j0 = nh * 8 + 2 * qc;
    float2 cpv[2][2];
    float  dtv[2][2];
    #pragma unroll
    for (int mt = 0; mt < 2; mt++)
        #pragma unroll
        for (int rs = 0; rs < 2; rs++) {
            size_t row = (size_t)row0 + mbase + mt * 16 + rs * 8 + qr;
            dtv[mt][rs] = delta_t[row];
            cpv[mt][rs] = *reinterpret_cast<const float2*>(c_prev + row * HID + j0);
        }

    __syncthreads();

    // ---- GEMM: per warp 32 rows (2 m-tiles) x 5 n-tiles (its column half) ----
    // n-tile for gate g is (2*g + nh); per kt: 8 A LDS + 10 B LDS + 10 HMMA
    float acc[5][2][4];
    #pragma unroll
    for (int g = 0; g < 5; g++)
        #pragma unroll
        for (int mt = 0; mt < 2; mt++)
            #pragma unroll
            for (int c = 0; c < 4; c++) acc[g][mt][c] = 0.0f;

    #pragma unroll
    for (int kt = 0; kt < 10; kt++) {
        uint32_t a[2][4];
        #pragma unroll
        for (int mt = 0; mt < 2; mt++) {
            int r = mbase + mt * 16 + qr;
            int k = kt * 8 + qc;
            a[mt][0] = As[r * SA + k];
            a[mt][1] = As[(r + 8) * SA + k];
            a[mt][2] = As[r * SA + k + 4];
            a[mt][3] = As[(r + 8) * SA + k + 4];
        }
        #pragma unroll
        for (int g = 0; g < 5; g++) {
            int n = (2 * g + nh) * 8 + qr;
            uint32_t b0 = Bs[(kt * 8 + qc) * SB + n];
            uint32_t b1 = Bs[(kt * 8 + qc + 4) * SB + n];
            mma_tf32(acc[g][0], a[0], b0, b1);
            mma_tf32(acc[g][1], a[1], b0, b1);
        }
    }

    // ---- epilogue: z col = g*16 + j0 + b  <- acc[g][mt][rs*2 + b] ----
    #pragma unroll
    for (int mt = 0; mt < 2; mt++) {
        #pragma unroll
        for (int rs = 0; rs < 2; rs++) {
            size_t row = (size_t)row0 + mbase + mt * 16 + rs * 8 + qr;
            float dt = dtv[mt][rs];
            float2 cp = cpv[mt][rs];
            float cpin[2] = {cp.x, cp.y};
            float h2[2], c2[2];
            #pragma unroll
            for (int b = 0; b < 2; b++) {
                int C = j0 + b;
                float zi = acc[0][mt][rs * 2 + b] + bs[C];
                float zf = acc[1][mt][rs * 2 + b] + bs[16 + C];
                float zo = acc[2][mt][rs * 2 + b] + bs[32 + C];
                float zc = acc[3][mt][rs * 2 + b] + bs[48 + C];
                float zd = acc[4][mt][rs * 2 + b] + bs[64 + C];
                float ig = tanh_approx(zi);
                float fg = tanh_approx(zf);
                float og = tanh_approx(zo);
                float ct = tanh_approx(zc);
                float decay = softplus_fast(zd);
                float cdec = cpin[b] * __expf(-decay * dt);
                float cn = fg * cdec + ig * ct;
                c2[b] = cn;
                h2[b] = og * tanh_approx(cn);
            }
            *reinterpret_cast<float2*>(out_h + row * HID + j0) = make_float2(h2[0], h2[1]);
            *reinterpret_cast<float2*>(out_c + row * HID + j0) = make_float2(c2[0], c2[1]);
        }
    }
}

extern "C" void kernel_launch(void* const* d_in, const int* in_sizes, int n_in,
                              void* d_out, int out_size) {
    const float* x      = (const float*)d_in[0];
    const float* h_prev = (const float*)d_in[1];
    const float* c_prev = (const float*)d_in[2];
    const float* dt     = (const float*)d_in[3];
    const float* W_i = (const float*)d_in[4];
    const float* b_i = (const float*)d_in[5];
    const float* W_f = (const float*)d_in[6];
    const float* b_f = (const float*)d_in[7];
    const float* W_o = (const float*)d_in[8];
    const float* b_o = (const float*)d_in[9];
    const float* W_c = (const float*)d_in[10];
    const float* b_c = (const float*)d_in[11];
    const float* W_d = (const float*)d_in[12];
    const float* b_d = (const float*)d_in[13];

    float* out_h = (float*)d_out;
    float* out_c = out_h + (size_t)out_size / 2;  // (h_next, c_next) concatenated

    cudaFuncSetAttribute(ctlstm_kernel, cudaFuncAttributeMaxDynamicSharedMemorySize, SMEM_BYTES);

    // one-time weight packing (cheap; graph-capturable, ordered before main)
    prep_kernel<<<(NDIM * KDIM + NDIM + 255) / 256, 256>>>(
        W_i, b_i, W_f, b_f, W_o, b_o, W_c, b_c, W_d, b_d);

    dim3 grid(BATCH_N / TILE_M);
    ctlstm_kernel<<<grid, NTHREADS, SMEM_BYTES>>>(
        x, h_prev, c_prev, dt, out_h, out_c);
}

// round 13
// speedup vs baseline: 1.3487x; 1.0736x over previous
#include <cuda_runtime.h>
#include <cstdint>

// ---------------- problem constants ----------------
#define BATCH_N   1048576
#define IN_SZ     64
#define HID       16
#define KDIM      80          // IN_SZ + HID
#define NDIM      80          // 5 * HID
#define TILE_M    128
#define NTHREADS  256
#define NTILES    (BATCH_N / TILE_M)   // 8192
#define GRID      296                  // 2 CTAs/SM, resident on 148- and 152-SM parts

// smem strides (in floats) chosen for conflict-free mma fragment LDS
#define SA 84                 // A: bank (20*qr + qc) % 32 all distinct over a warp
#define SB 88                 // B: bank (24*qc + qr + 8*(t%4)) % 32 all distinct

#define A_FLOATS (TILE_M * SA)        // 10752 (one buffer)
#define B_FLOATS (KDIM * SB)          // 7040
#define SMEM_FLOATS (2 * A_FLOATS + B_FLOATS + NDIM)
#define SMEM_BYTES  (SMEM_FLOATS * 4) // 114496 -> 2 CTAs/SM

// ---------------- precomputed weights (written by prep kernel) ----------------
__device__ uint32_t g_Bp[B_FLOATS];    // tf32 W as [k][n], stride SB
__device__ float    g_bias[NDIM];

static __device__ __forceinline__ uint32_t f2tf32(float f) {
    uint32_t u;
    asm("cvt.rna.tf32.f32 %0, %1;" : "=r"(u) : "f"(f));
    return u;
}
static __device__ __forceinline__ uint32_t smem_u32(const void* p) {
    uint32_t a;
    asm("{ .reg .u64 t; cvta.to.shared.u64 t, %1; cvt.u32.u64 %0, t; }" : "=r"(a) : "l"(p));
    return a;
}

static __device__ __forceinline__ void mma_tf32(float* c, const uint32_t* a,
                                                uint32_t b0, uint32_t b1) {
    asm volatile(
        "mma.sync.aligned.m16n8k8.row.col.f32.tf32.tf32.f32 "
        "{%0,%1,%2,%3}, {%4,%5,%6,%7}, {%8,%9}, {%0,%1,%2,%3};"
        : "+f"(c[0]), "+f"(c[1]), "+f"(c[2]), "+f"(c[3])
        : "r"(a[0]), "r"(a[1]), "r"(a[2]), "r"(a[3]), "r"(b0), "r"(b1));
}

// single-instruction tanh (MUFU.TANH) — validated: rel_err unchanged vs exact
static __device__ __forceinline__ float tanh_approx(float x) {
    float y;
    asm("tanh.approx.f32 %0, %1;" : "=f"(y) : "f"(x));
    return y;
}
static __device__ __forceinline__ float softplus_fast(float x) {
    return fmaxf(x, 0.0f) + __logf(1.0f + __expf(-fabsf(x)));
}

// cp.async 16B, L1-bypassing
static __device__ __forceinline__ void cp_async16(uint32_t daddr, const void* src) {
    asm volatile("cp.async.cg.shared.global [%0], [%1], 16;" :: "r"(daddr), "l"(src));
}

// issue the full A-tile fill (raw fp32) for tile starting at row0 into dst buffer
static __device__ __forceinline__ void a_fill_async(float* dst, int row0,
                                                    const float* __restrict__ x,
                                                    const float* __restrict__ h,
                                                    int tid) {
    #pragma unroll
    for (int it = 0; it < 10; it++) {              // 2560 float4 items / 256 threads
        int item = it * NTHREADS + tid;
        int r = item / 20;                          // 0..127
        int c = item - r * 20;                      // 0..19 (float4 index)
        const float* src = (c < 16)
            ? (x + (size_t)(row0 + r) * IN_SZ + c * 4)
            : (h + (size_t)(row0 + r) * HID + (c - 16) * 4);
        cp_async16(smem_u32(dst + r * SA + c * 4), src);
    }
}

// ---------------- prep: pack W -> tf32 [k][n] stride SB, bias ----------------
__global__ void prep_kernel(
    const float* __restrict__ W_i, const float* __restrict__ b_i,
    const float* __restrict__ W_f, const float* __restrict__ b_f,
    const float* __restrict__ W_o, const float* __restrict__ b_o,
    const float* __restrict__ W_c, const float* __restrict__ b_c,
    const float* __restrict__ W_d, const float* __restrict__ b_d)
{
    int idx = blockIdx.x * blockDim.x + threadIdx.x;
    if (idx < NDIM * KDIM) {
        int k = idx / NDIM;
        int n = idx - k * NDIM;
        int g = n >> 4, c = n & 15;
        const float* W = (g == 0) ? W_i : (g == 1) ? W_f : (g == 2) ? W_o
                       : (g == 3) ? W_c : W_d;
        g_Bp[k * SB + n] = f2tf32(W[k * HID + c]);
    } else if (idx < NDIM * KDIM + NDIM) {
        int n = idx - NDIM * KDIM;
        int g = n >> 4, c = n & 15;
        const float* B = (g == 0) ? b_i : (g == 1) ? b_f : (g == 2) ? b_o
                       : (g == 3) ? b_c : b_d;
        g_bias[n] = B[c];
    }
    if (idx < KDIM) {
        #pragma unroll
        for (int p = NDIM; p < SB; p++) g_Bp[idx * SB + p] = 0u;
    }
}

__global__ void __launch_bounds__(NTHREADS, 2) ctlstm_kernel(
    const float* __restrict__ x,
    const float* __restrict__ h_prev,
    const float* __restrict__ c_prev,
    const float* __restrict__ delta_t,
    float* __restrict__ out_h, float* __restrict__ out_c)
{
    extern __shared__ float smemf[];
    float*    Af = smemf;                                  // [2][128][SA] raw fp32
    uint32_t* Bs = reinterpret_cast<uint32_t*>(smemf + 2 * A_FLOATS); // [80][SB] tf32
    float*    bs = reinterpret_cast<float*>(Bs + B_FLOATS);           // bias[80]

    const int tid  = threadIdx.x;
    const int warp = tid >> 5;
    const int lane = tid & 31;
    const int qr   = lane >> 2;   // 0..7
    const int qc   = lane & 3;    // 0..3

    // N-split warp pairing (R12): rg picks 32-row group, nh picks column half
    const int rg = warp & 3;
    const int nh = warp >> 2;
    const int mbase = rg * 32;
    const int j0 = nh * 8 + 2 * qc;

    // ---- one-time per CTA: B + bias into smem (coalesced, L2-hot) ----
    {
        const uint4* src = reinterpret_cast<const uint4*>(g_Bp);
        uint4* dst = reinterpret_cast<uint4*>(Bs);
        #pragma unroll
        for (int it = 0; it < B_FLOATS / 4 / NTHREADS + 1; it++) {
            int i = it * NTHREADS + tid;
            if (i < B_FLOATS / 4) dst[i] = src[i];
        }
        if (tid < NDIM) bs[tid] = g_bias[tid];
    }

    // ---- prologue: async-load first tile into buffer 0 ----
    int tile = blockIdx.x;
    if (tile < NTILES) a_fill_async(Af, tile * TILE_M, x, h_prev, tid);
    asm volatile("cp.async.commit_group;" ::: "memory");

    int it = 0;
    for (; tile < NTILES; tile += GRID, it++) {
        const int buf = it & 1;
        const int row0 = tile * TILE_M;

        // ---- prefetch epilogue operands for this tile (overlaps async wait) ----
        float2 cpv[2][2];
        float  dtv[2][2];
        #pragma unroll
        for (int mt = 0; mt < 2; mt++)
            #pragma unroll
            for (int rs = 0; rs < 2; rs++) {
                size_t row = (size_t)row0 + mbase + mt * 16 + rs * 8 + qr;
                dtv[mt][rs] = delta_t[row];
                cpv[mt][rs] = *reinterpret_cast<const float2*>(c_prev + row * HID + j0);
            }

        // barrier #1: all warps finished previous compute (which used buf^1)
        __syncthreads();

        // ---- issue next tile's fill into the other buffer ----
        int ntile = tile + GRID;
        if (ntile < NTILES)
            a_fill_async(Af + (buf ^ 1) * A_FLOATS, ntile * TILE_M, x, h_prev, tid);
        asm volatile("cp.async.commit_group;" ::: "memory");

        // wait for THIS tile's data (allow 1 outstanding group = the next tile)
        asm volatile("cp.async.wait_group 1;" ::: "memory");
        __syncthreads();   // barrier #2: tile data visible to all warps (also covers B copy at it=0)

        // ---- GEMM: per warp 32 rows (2 m-tiles) x its 5 n-tiles ----
        const float* As = Af + buf * A_FLOATS;
        float acc[5][2][4];
        #pragma unroll
        for (int g = 0; g < 5; g++)
            #pragma unroll
            for (int mt = 0; mt < 2; mt++)
                #pragma unroll
                for (int c = 0; c < 4; c++) acc[g][mt][c] = 0.0f;

        #pragma unroll
        for (int kt = 0; kt < 10; kt++) {
            uint32_t a[2][4];
            #pragma unroll
            for (int mt = 0; mt < 2; mt++) {
                int r = mbase + mt * 16 + qr;
                int k = kt * 8 + qc;
                a[mt][0] = f2tf32(As[r * SA + k]);
                a[mt][1] = f2tf32(As[(r + 8) * SA + k]);
                a[mt][2] = f2tf32(As[r * SA + k + 4]);
                a[mt][3] = f2tf32(As[(r + 8) * SA + k + 4]);
            }
            #pragma unroll
            for (int g = 0; g < 5; g++) {
                int n = (2 * g + nh) * 8 + qr;
                uint32_t b0 = Bs[(kt * 8 + qc) * SB + n];
                uint32_t b1 = Bs[(kt * 8 + qc + 4) * SB + n];
                mma_tf32(acc[g][0], a[0], b0, b1);
                mma_tf32(acc[g][1], a[1], b0, b1);
            }
        }

        // ---- epilogue: z col = g*16 + j0 + b  <- acc[g][mt][rs*2 + b] ----
        #pragma unroll
        for (int mt = 0; mt < 2; mt++) {
            #pragma unroll
            for (int rs = 0; rs < 2; rs++) {
                size_t row = (size_t)row0 + mbase + mt * 16 + rs * 8 + qr;
                float dt = dtv[mt][rs];
                float2 cp = cpv[mt][rs];
                float cpin[2] = {cp.x, cp.y};
                float h2[2], c2[2];
                #pragma unroll
                for (int b = 0; b < 2; b++) {
                    int C = j0 + b;
                    float zi = acc[0][mt][rs * 2 + b] + bs[C];
                    float zf = acc[1][mt][rs * 2 + b] + bs[16 + C];
                    float zo = acc[2][mt][rs * 2 + b] + bs[32 + C];
                    float zc = acc[3][mt][rs * 2 + b] + bs[48 + C];
                    float zd = acc[4][mt][rs * 2 + b] + bs[64 + C];
                    float ig = tanh_approx(zi);
                    float fg = tanh_approx(zf);
                    float og = tanh_approx(zo);
                    float ct = tanh_approx(zc);
                    float decay = softplus_fast(zd);
                    float cdec = cpin[b] * __expf(-decay * dt);
                    float cn = fg * cdec + ig * ct;
                    c2[b] = cn;
                    h2[b] = og * tanh_approx(cn);
                }
                *reinterpret_cast<float2*>(out_h + row * HID + j0) = make_float2(h2[0], h2[1]);
                *reinterpret_cast<float2*>(out_c + row * HID + j0) = make_float2(c2[0], c2[1]);
            }
        }
    }
}

extern "C" void kernel_launch(void* const* d_in, const int* in_sizes, int n_in,
                              void* d_out, int out_size) {
    const float* x      = (const float*)d_in[0];
    const float* h_prev = (const float*)d_in[1];
    const float* c_prev = (const float*)d_in[2];
    const float* dt     = (const float*)d_in[3];
    const float* W_i = (const float*)d_in[4];
    const float* b_i = (const float*)d_in[5];
    const float* W_f = (const float*)d_in[6];
    const float* b_f = (const float*)d_in[7];
    const float* W_o = (const float*)d_in[8];
    const float* b_o = (const float*)d_in[9];
    const float* W_c = (const float*)d_in[10];
    const float* b_c = (const float*)d_in[11];
    const float* W_d = (const float*)d_in[12];
    const float* b_d = (const float*)d_in[13];

    float* out_h = (float*)d_out;
    float* out_c = out_h + (size_t)out_size / 2;  // (h_next, c_next) concatenated

    cudaFuncSetAttribute(ctlstm_kernel, cudaFuncAttributeMaxDynamicSharedMemorySize, SMEM_BYTES);

    // one-time weight packing (cheap; graph-capturable, ordered before main)
    prep_kernel<<<(NDIM * KDIM + NDIM + 255) / 256, 256>>>(
        W_i, b_i, W_f, b_f, W_o, b_o, W_c, b_c, W_d, b_d);

    ctlstm_kernel<<<GRID, NTHREADS, SMEM_BYTES>>>(
        x, h_prev, c_prev, dt, out_h, out_c);
}

// round 14
// speedup vs baseline: 1.3921x; 1.0321x over previous
#include <cuda_runtime.h>
#include <cstdint>

// ---------------- problem constants ----------------
#define BATCH_N   1048576
#define IN_SZ     64
#define HID       16
#define KDIM      80          // IN_SZ + HID
#define NDIM      80          // 5 * HID
#define TILE_M    128
#define NTHREADS  256
#define NTILES    (BATCH_N / TILE_M)   // 8192
#define GRID      304                  // 2 CTAs/SM on GB300's 152 SMs

// smem stride for A (floats): conflict-free scalar fragment LDS
#define SA 84                 // bank (20*qr + qc) % 32 all distinct over a warp

#define A_FLOATS (TILE_M * SA)        // 10752 (one buffer)
// B pairs: [kt=10][g=5][nh=2][lane=32] x float2 = 6400 floats
#define BPAIR_FLOATS 6400
#define SMEM_FLOATS (2 * A_FLOATS + BPAIR_FLOATS + NDIM)
#define SMEM_BYTES  (SMEM_FLOATS * 4) // 111936 (~109.3 KB) -> 2 CTAs/SM

// ---------------- precomputed weights (written by prep kernel) ----------------
__device__ uint32_t g_Bp[BPAIR_FLOATS];  // tf32 B-fragment pairs, per-thread layout
__device__ float    g_bias[NDIM];

static __device__ __forceinline__ uint32_t f2tf32(float f) {
    uint32_t u;
    asm("cvt.rna.tf32.f32 %0, %1;" : "=r"(u) : "f"(f));
    return u;
}
static __device__ __forceinline__ uint32_t smem_u32(const void* p) {
    uint32_t a;
    asm("{ .reg .u64 t; cvta.to.shared.u64 t, %1; cvt.u32.u64 %0, t; }" : "=r"(a) : "l"(p));
    return a;
}

static __device__ __forceinline__ void mma_tf32(float* c, const uint32_t* a,
                                                uint32_t b0, uint32_t b1) {
    asm volatile(
        "mma.sync.aligned.m16n8k8.row.col.f32.tf32.tf32.f32 "
        "{%0,%1,%2,%3}, {%4,%5,%6,%7}, {%8,%9}, {%0,%1,%2,%3};"
        : "+f"(c[0]), "+f"(c[1]), "+f"(c[2]), "+f"(c[3])
        : "r"(a[0]), "r"(a[1]), "r"(a[2]), "r"(a[3]), "r"(b0), "r"(b1));
}

// single-instruction tanh (MUFU.TANH) — validated: rel_err unchanged vs exact
static __device__ __forceinline__ float tanh_approx(float x) {
    float y;
    asm("tanh.approx.f32 %0, %1;" : "=f"(y) : "f"(x));
    return y;
}
static __device__ __forceinline__ float softplus_fast(float x) {
    return fmaxf(x, 0.0f) + __logf(1.0f + __expf(-fabsf(x)));
}

// cp.async 16B, L1-bypassing
static __device__ __forceinline__ void cp_async16(uint32_t daddr, const void* src) {
    asm volatile("cp.async.cg.shared.global [%0], [%1], 16;" :: "r"(daddr), "l"(src));
}

// issue the full A-tile fill (raw fp32) for tile starting at row0 into dst buffer
static __device__ __forceinline__ void a_fill_async(float* dst, int row0,
                                                    const float* __restrict__ x,
                                                    const float* __restrict__ h,
                                                    int tid) {
    #pragma unroll
    for (int it = 0; it < 10; it++) {              // 2560 float4 items / 256 threads
        int item = it * NTHREADS + tid;
        int r = item / 20;                          // 0..127
        int c = item - r * 20;                      // 0..19 (float4 index)
        const float* src = (c < 16)
            ? (x + (size_t)(row0 + r) * IN_SZ + c * 4)
            : (h + (size_t)(row0 + r) * HID + (c - 16) * 4);
        cp_async16(smem_u32(dst + r * SA + c * 4), src);
    }
}

// ---------------- prep: pack W into per-thread LDS.64 B-pairs + bias ----------------
// g_Bp index i: p = i&1; lane = (i>>1)&31; nh = (i>>6)&1; rest = i>>7; g = rest%5; kt = rest/5
//   qr = lane>>2, qc = lane&3
//   value = tf32( W_g[k = kt*8 + qc + 4*p][col = nh*8 + qr] )
__global__ void prep_kernel(
    const float* __restrict__ W_i, const float* __restrict__ b_i,
    const float* __restrict__ W_f, const float* __restrict__ b_f,
    const float* __restrict__ W_o, const float* __restrict__ b_o,
    const float* __restrict__ W_c, const float* __restrict__ b_c,
    const float* __restrict__ W_d, const float* __restrict__ b_d)
{
    int i = blockIdx.x * blockDim.x + threadIdx.x;
    if (i < BPAIR_FLOATS) {
        int p    = i & 1;
        int lane = (i >> 1) & 31;
        int nh   = (i >> 6) & 1;
        int rest = i >> 7;            // 0..49
        int g  = rest % 5;
        int kt = rest / 5;
        int qr = lane >> 2;
        int qc = lane & 3;
        int k   = kt * 8 + qc + 4 * p;
        int col = nh * 8 + qr;
        const float* W = (g == 0) ? W_i : (g == 1) ? W_f : (g == 2) ? W_o
                       : (g == 3) ? W_c : W_d;
        g_Bp[i] = f2tf32(W[k * HID + col]);
    } else if (i < BPAIR_FLOATS + NDIM) {
        int n = i - BPAIR_FLOATS;
        int g = n >> 4, c = n & 15;
        const float* B = (g == 0) ? b_i : (g == 1) ? b_f : (g == 2) ? b_o
                       : (g == 3) ? b_c : b_d;
        g_bias[n] = B[c];
    }
}

__global__ void __launch_bounds__(NTHREADS, 2) ctlstm_kernel(
    const float* __restrict__ x,
    const float* __restrict__ h_prev,
    const float* __restrict__ c_prev,
    const float* __restrict__ delta_t,
    float* __restrict__ out_h, float* __restrict__ out_c)
{
    extern __shared__ float smemf[];
    float*    Af = smemf;                                  // [2][128][SA] raw fp32
    uint32_t* Bs = reinterpret_cast<uint32_t*>(smemf + 2 * A_FLOATS); // B pairs
    float*    bs = reinterpret_cast<float*>(Bs + BPAIR_FLOATS);       // bias[80]

    const int tid  = threadIdx.x;
    const int warp = tid >> 5;
    const int lane = tid & 31;
    const int qr   = lane >> 2;   // 0..7
    const int qc   = lane & 3;    // 0..3

    // N-split warp pairing: rg picks 32-row group, nh picks column half
    const int rg = warp & 3;
    const int nh = warp >> 2;
    const int mbase = rg * 32;
    const int j0 = nh * 8 + 2 * qc;

    // ---- one-time per CTA: B pairs + bias into smem (coalesced, L2-hot) ----
    {
        const uint4* src = reinterpret_cast<const uint4*>(g_Bp);
        uint4* dst = reinterpret_cast<uint4*>(Bs);
        #pragma unroll
        for (int it = 0; it < 7; it++) {
            int i = it * NTHREADS + tid;
            if (i < BPAIR_FLOATS / 4) dst[i] = src[i];
        }
        if (tid < NDIM) bs[tid] = g_bias[tid];
    }

    // per-thread B base: pairs at (nh*32 + lane), stride 64 float2 per (kt,g)
    const uint2* Bp2 = reinterpret_cast<const uint2*>(Bs) + nh * 32 + lane;

    // ---- prologue: async-load first tile into buffer 0 ----
    int tile = blockIdx.x;
    if (tile < NTILES) a_fill_async(Af, tile * TILE_M, x, h_prev, tid);
    asm volatile("cp.async.commit_group;" ::: "memory");

    int it = 0;
    for (; tile < NTILES; tile += GRID, it++) {
        const int buf = it & 1;
        const int row0 = tile * TILE_M;

        // ---- prefetch epilogue operands for this tile (overlaps async wait) ----
        float2 cpv[2][2];
        float  dtv[2][2];
        #pragma unroll
        for (int mt = 0; mt < 2; mt++)
            #pragma unroll
            for (int rs = 0; rs < 2; rs++) {
                size_t row = (size_t)row0 + mbase + mt * 16 + rs * 8 + qr;
                dtv[mt][rs] = delta_t[row];
                cpv[mt][rs] = *reinterpret_cast<const float2*>(c_prev + row * HID + j0);
            }

        // barrier #1: all warps finished previous compute (which used buf^1)
        __syncthreads();

        // ---- issue next tile's fill into the other buffer ----
        int ntile = tile + GRID;
        if (ntile < NTILES)
            a_fill_async(Af + (buf ^ 1) * A_FLOATS, ntile * TILE_M, x, h_prev, tid);
        asm volatile("cp.async.commit_group;" ::: "memory");

        // wait for THIS tile's data (allow 1 outstanding group = the next tile)
        asm volatile("cp.async.wait_group 1;" ::: "memory");
        __syncthreads();   // barrier #2: tile data visible to all warps (covers B copy at it=0)

        // ---- GEMM: per warp 32 rows (2 m-tiles) x its 5 n-tiles ----
        // per kt: 8 A LDS.32 + 5 B LDS.64 + 8 cvt + 10 HMMA
        const float* As = Af + buf * A_FLOATS;
        float acc[5][2][4];
        #pragma unroll
        for (int g = 0; g < 5; g++)
            #pragma unroll
            for (int mt = 0; mt < 2; mt++)
                #pragma unroll
                for (int c = 0; c < 4; c++) acc[g][mt][c] = 0.0f;

        #pragma unroll
        for (int kt = 0; kt < 10; kt++) {
            uint32_t a[2][4];
            #pragma unroll
            for (int mt = 0; mt < 2; mt++) {
                int r = mbase + mt * 16 + qr;
                int k = kt * 8 + qc;
                a[mt][0] = f2tf32(As[r * SA + k]);
                a[mt][1] = f2tf32(As[(r + 8) * SA + k]);
                a[mt][2] = f2tf32(As[r * SA + k + 4]);
                a[mt][3] = f2tf32(As[(r + 8) * SA + k + 4]);
            }
            #pragma unroll
            for (int g = 0; g < 5; g++) {
                uint2 bv = Bp2[(kt * 5 + g) * 64];
                mma_tf32(acc[g][0], a[0], bv.x, bv.y);
                mma_tf32(acc[g][1], a[1], bv.x, bv.y);
            }
        }

        // ---- epilogue: z col = g*16 + j0 + b  <- acc[g][mt][rs*2 + b] ----
        #pragma unroll
        for (int mt = 0; mt < 2; mt++) {
            #pragma unroll
            for (int rs = 0; rs < 2; rs++) {
                size_t row = (size_t)row0 + mbase + mt * 16 + rs * 8 + qr;
                float dt = dtv[mt][rs];
                float2 cp = cpv[mt][rs];
                float cpin[2] = {cp.x, cp.y};
                float h2[2], c2[2];
                #pragma unroll
                for (int b = 0; b < 2; b++) {
                    int C = j0 + b;
                    float zi = acc[0][mt][rs * 2 + b] + bs[C];
                    float zf = acc[1][mt][rs * 2 + b] + bs[16 + C];
                    float zo = acc[2][mt][rs * 2 + b] + bs[32 + C];
                    float zc = acc[3][mt][rs * 2 + b] + bs[48 + C];
                    float zd = acc[4][mt][rs * 2 + b] + bs[64 + C];
                    float ig = tanh_approx(zi);
                    float fg = tanh_approx(zf);
                    float og = tanh_approx(zo);
                    float ct = tanh_approx(zc);
                    float decay = softplus_fast(zd);
                    float cdec = cpin[b] * __expf(-decay * dt);
                    float cn = fg * cdec + ig * ct;
                    c2[b] = cn;
                    h2[b] = og * tanh_approx(cn);
                }
                *reinterpret_cast<float2*>(out_h + row * HID + j0) = make_float2(h2[0], h2[1]);
                *reinterpret_cast<float2*>(out_c + row * HID + j0) = make_float2(c2[0], c2[1]);
            }
        }
    }
}

extern "C" void kernel_launch(void* const* d_in, const int* in_sizes, int n_in,
                              void* d_out, int out_size) {
    const float* x      = (const float*)d_in[0];
    const float* h_prev = (const float*)d_in[1];
    const float* c_prev = (const float*)d_in[2];
    const float* dt     = (const float*)d_in[3];
    const float* W_i = (const float*)d_in[4];
    const float* b_i = (const float*)d_in[5];
    const float* W_f = (const float*)d_in[6];
    const float* b_f = (const float*)d_in[7];
    const float* W_o = (const float*)d_in[8];
    const float* b_o = (const float*)d_in[9];
    const float* W_c = (const float*)d_in[10];
    const float* b_c = (const float*)d_in[11];
    const float* W_d = (const float*)d_in[12];
    const float* b_d = (const float*)d_in[13];

    float* out_h = (float*)d_out;
    float* out_c = out_h + (size_t)out_size / 2;  // (h_next, c_next) concatenated

    cudaFuncSetAttribute(ctlstm_kernel, cudaFuncAttributeMaxDynamicSharedMemorySize, SMEM_BYTES);

    // one-time weight packing (cheap; graph-capturable, ordered before main)
    prep_kernel<<<(BPAIR_FLOATS + NDIM + 255) / 256, 256>>>(
        W_i, b_i, W_f, b_f, W_o, b_o, W_c, b_c, W_d, b_d);

    ctlstm_kernel<<<GRID, NTHREADS, SMEM_BYTES>>>(
        x, h_prev, c_prev, dt, out_h, out_c);
}